// round 1
// baseline (speedup 1.0000x reference)
#include <cuda_runtime.h>
#include <cstdint>

#define N_NODES 100000
#define N_EDGES 1000000
#define IN_CH   32
#define EDGE_CH 16
#define OUT_CH  32
#define D_MID   56

// Scratch (device globals — no allocation allowed)
static __device__ int   g_is64;
static __device__ float g_XR[N_NODES * D_MID];  // x @ W1[0:32]  + b1
static __device__ float g_XC[N_NODES * D_MID];  // x @ W1[32:64]

// ---------------------------------------------------------------------------
// K0: detect whether edge_index is int64 (odd 32-bit words all zero) or int32
// ---------------------------------------------------------------------------
__global__ void k_detect(const unsigned int* __restrict__ w) {
    __shared__ int bad;
    if (threadIdx.x == 0) bad = 0;
    __syncthreads();
    for (int i = threadIdx.x; i < 4096; i += blockDim.x)
        if (w[2 * i + 1] != 0u) bad = 1;   // benign race; any writer writes 1
    __syncthreads();
    if (threadIdx.x == 0) g_is64 = !bad;
}

// ---------------------------------------------------------------------------
// K1: init output to -inf (atomic max identity)
// ---------------------------------------------------------------------------
__global__ void k_init(unsigned int* __restrict__ out) {
    int i = blockIdx.x * blockDim.x + threadIdx.x;
    if (i < N_NODES * OUT_CH) out[i] = 0xFF800000u;  // -inf
}

// ---------------------------------------------------------------------------
// K2: per-node precompute.  which==0: XR = x@W1[0:32]+b1 ; which==1: XC = x@W1[32:64]
// ---------------------------------------------------------------------------
__global__ void __launch_bounds__(128) k_node(const float* __restrict__ x,
                                              const float* __restrict__ W1,
                                              const float* __restrict__ b1,
                                              int which) {
    __shared__ float sW[IN_CH * D_MID];  // 32*56*4 = 7168 B
    __shared__ float sb[D_MID];
    const float* Wsrc = W1 + which * IN_CH * D_MID;
    for (int i = threadIdx.x; i < IN_CH * D_MID; i += blockDim.x) sW[i] = Wsrc[i];
    for (int i = threadIdx.x; i < D_MID; i += blockDim.x) sb[i] = (which == 0) ? b1[i] : 0.0f;
    __syncthreads();

    int n = blockIdx.x * blockDim.x + threadIdx.x;
    if (n >= N_NODES) return;

    float xr[IN_CH];
    const float4* xp = reinterpret_cast<const float4*>(x + n * IN_CH);
#pragma unroll
    for (int c = 0; c < 8; c++) {
        float4 v = xp[c];
        xr[4 * c + 0] = v.x; xr[4 * c + 1] = v.y; xr[4 * c + 2] = v.z; xr[4 * c + 3] = v.w;
    }

    float h[D_MID];
#pragma unroll
    for (int j = 0; j < D_MID; j++) h[j] = sb[j];
#pragma unroll
    for (int k = 0; k < IN_CH; k++) {
        float a = xr[k];
        const float* w = &sW[k * D_MID];
#pragma unroll
        for (int j = 0; j < D_MID; j += 4) {
            float4 ww = *reinterpret_cast<const float4*>(w + j);
            h[j + 0] += a * ww.x; h[j + 1] += a * ww.y;
            h[j + 2] += a * ww.z; h[j + 3] += a * ww.w;
        }
    }

    float* dst = (which == 0 ? g_XR : g_XC) + n * D_MID;
#pragma unroll
    for (int j = 0; j < D_MID; j += 4) {
        *reinterpret_cast<float4*>(dst + j) = make_float4(h[j], h[j + 1], h[j + 2], h[j + 3]);
    }
}

// ---------------------------------------------------------------------------
// K3: per-edge MLP + scatter-max
// ---------------------------------------------------------------------------
__device__ __forceinline__ void atomicMaxF(float* addr, float val) {
    if (val >= 0.0f) atomicMax(reinterpret_cast<int*>(addr), __float_as_int(val));
    else             atomicMin(reinterpret_cast<unsigned int*>(addr), __float_as_uint(val));
}

__global__ void __launch_bounds__(128) k_edge(const int* __restrict__ idx32,
                                              const float* __restrict__ edge_attr,
                                              const float* __restrict__ W1,
                                              const float* __restrict__ W2,
                                              const float* __restrict__ b2,
                                              float* __restrict__ out) {
    __shared__ float sWe[EDGE_CH * D_MID];  // W1 rows 64..79  (3584 B)
    __shared__ float sW2[D_MID * OUT_CH];   // 7168 B
    __shared__ float sb2[OUT_CH];

    const float* We = W1 + 2 * IN_CH * D_MID;
    for (int i = threadIdx.x; i < EDGE_CH * D_MID; i += blockDim.x) sWe[i] = We[i];
    for (int i = threadIdx.x; i < D_MID * OUT_CH; i += blockDim.x) sW2[i] = W2[i];
    for (int i = threadIdx.x; i < OUT_CH; i += blockDim.x) sb2[i] = b2[i];
    __syncthreads();

    int e = blockIdx.x * blockDim.x + threadIdx.x;
    if (e >= N_EDGES) return;

    int rol, col;
    if (g_is64) {
        rol = idx32[2 * e];
        col = idx32[2 * (N_EDGES + e)];
    } else {
        rol = idx32[e];
        col = idx32[N_EDGES + e];
    }

    // h = XR[rol] + XC[col]
    float h[D_MID];
    const float4* pr = reinterpret_cast<const float4*>(g_XR + rol * D_MID);
    const float4* pc = reinterpret_cast<const float4*>(g_XC + col * D_MID);
#pragma unroll
    for (int j = 0; j < D_MID / 4; j++) {
        float4 a = pr[j], b = pc[j];
        h[4 * j + 0] = a.x + b.x; h[4 * j + 1] = a.y + b.y;
        h[4 * j + 2] = a.z + b.z; h[4 * j + 3] = a.w + b.w;
    }

    // h += edge_attr[e] @ W1[64:80]
    const float4* pe = reinterpret_cast<const float4*>(edge_attr + e * EDGE_CH);
#pragma unroll
    for (int c = 0; c < 4; c++) {
        float4 v = pe[c];
        float av[4] = {v.x, v.y, v.z, v.w};
#pragma unroll
        for (int u = 0; u < 4; u++) {
            float a = av[u];
            const float* w = &sWe[(4 * c + u) * D_MID];
#pragma unroll
            for (int j = 0; j < D_MID; j += 4) {
                float4 ww = *reinterpret_cast<const float4*>(w + j);
                h[j + 0] += a * ww.x; h[j + 1] += a * ww.y;
                h[j + 2] += a * ww.z; h[j + 3] += a * ww.w;
            }
        }
    }

    // LeakyReLU(0.01)
#pragma unroll
    for (int j = 0; j < D_MID; j++) h[j] = h[j] > 0.0f ? h[j] : 0.01f * h[j];

    float* orow = out + col * OUT_CH;

    // Layer 2 in two halves of 16 outputs to bound register pressure
#pragma unroll
    for (int half = 0; half < 2; half++) {
        float o[16];
#pragma unroll
        for (int j = 0; j < 16; j++) o[j] = sb2[half * 16 + j];
#pragma unroll
        for (int k = 0; k < D_MID; k++) {
            float a = h[k];
            const float* w = &sW2[k * OUT_CH + half * 16];
#pragma unroll
            for (int j = 0; j < 16; j += 4) {
                float4 ww = *reinterpret_cast<const float4*>(w + j);
                o[j + 0] += a * ww.x; o[j + 1] += a * ww.y;
                o[j + 2] += a * ww.z; o[j + 3] += a * ww.w;
            }
        }
#pragma unroll
        for (int j = 0; j < 16; j++) {
            float v = o[j] > 0.0f ? o[j] : 0.01f * o[j];
            float* addr = orow + half * 16 + j;
            float cur = *addr;                 // monotone max: stale read only
            if (v > cur) atomicMaxF(addr, v);  // weakens the filter, never wrong
        }
    }
}

// ---------------------------------------------------------------------------
// K4: finalize — replace -inf with 0, elementwise max with x (IN_CH==OUT_CH)
// ---------------------------------------------------------------------------
__global__ void k_final(const float* __restrict__ x, float* __restrict__ out) {
    int i = blockIdx.x * blockDim.x + threadIdx.x;
    if (i >= N_NODES * OUT_CH) return;
    float a = out[i];
    if (__float_as_uint(a) == 0xFF800000u) a = 0.0f;
    out[i] = fmaxf(a, x[i]);
}

// ---------------------------------------------------------------------------
extern "C" void kernel_launch(void* const* d_in, const int* in_sizes, int n_in,
                              void* d_out, int out_size) {
    const float* x         = (const float*)d_in[0];
    const int*   idx32     = (const int*)d_in[1];
    const float* edge_attr = (const float*)d_in[2];
    const float* W1        = (const float*)d_in[3];
    const float* b1        = (const float*)d_in[4];
    const float* W2        = (const float*)d_in[5];
    const float* b2        = (const float*)d_in[6];
    float* out = (float*)d_out;

    k_detect<<<1, 256>>>((const unsigned int*)d_in[1]);
    k_init<<<(N_NODES * OUT_CH + 255) / 256, 256>>>((unsigned int*)d_out);
    k_node<<<(N_NODES + 127) / 128, 128>>>(x, W1, b1, 0);
    k_node<<<(N_NODES + 127) / 128, 128>>>(x, W1, b1, 1);
    k_edge<<<(N_EDGES + 127) / 128, 128>>>(idx32, edge_attr, W1, W2, b2, out);
    k_final<<<(N_NODES * OUT_CH + 255) / 256, 256>>>(x, out);
}

// round 2
// speedup vs baseline: 1.4280x; 1.4280x over previous
#include <cuda_runtime.h>
#include <cstdint>

#define N_NODES 100000
#define N_EDGES 1000000
#define IN_CH   32
#define EDGE_CH 16
#define OUT_CH  32
#define D_MID   56

typedef unsigned long long u64;

static __device__ int   g_is64;
static __device__ __align__(16) float g_XR[N_NODES * D_MID];  // x @ W1[0:32]  + b1
static __device__ __align__(16) float g_XC[N_NODES * D_MID];  // x @ W1[32:64]

// ---- packed f32x2 helpers ---------------------------------------------------
__device__ __forceinline__ u64 pk2(float a, float b) {
    u64 r; asm("mov.b64 %0, {%1,%2};" : "=l"(r) : "f"(a), "f"(b)); return r;
}
__device__ __forceinline__ void upk2(float& a, float& b, u64 v) {
    asm("mov.b64 {%0,%1}, %2;" : "=f"(a), "=f"(b) : "l"(v));
}
#define FMA2(d, a, b, c) asm("fma.rn.f32x2 %0, %1, %2, %3;" : "=l"(d) : "l"(a), "l"(b), "l"(c))
#define ADD2(d, a, b)    asm("add.rn.f32x2 %0, %1, %2;"     : "=l"(d) : "l"(a), "l"(b))

// ---------------------------------------------------------------------------
// K0: detect int64 vs int32 edge_index (odd 32-bit words all zero <=> int64)
// ---------------------------------------------------------------------------
__global__ void k_detect(const unsigned int* __restrict__ w) {
    __shared__ int bad;
    if (threadIdx.x == 0) bad = 0;
    __syncthreads();
    for (int i = threadIdx.x; i < 4096; i += blockDim.x)
        if (w[2 * i + 1] != 0u) bad = 1;
    __syncthreads();
    if (threadIdx.x == 0) g_is64 = !bad;
}

// ---------------------------------------------------------------------------
// K1: init output to -inf
// ---------------------------------------------------------------------------
__global__ void k_init(unsigned int* __restrict__ out) {
    int i = blockIdx.x * blockDim.x + threadIdx.x;
    if (i < N_NODES * OUT_CH) out[i] = 0xFF800000u;
}

// ---------------------------------------------------------------------------
// K2: per-node precompute with f32x2
// ---------------------------------------------------------------------------
__global__ void __launch_bounds__(128) k_node(const float* __restrict__ x,
                                              const float* __restrict__ W1,
                                              const float* __restrict__ b1,
                                              int which) {
    __shared__ __align__(16) float sW[IN_CH * D_MID];
    __shared__ __align__(16) float sb[D_MID];
    const float* Wsrc = W1 + which * IN_CH * D_MID;
    for (int i = threadIdx.x; i < IN_CH * D_MID; i += blockDim.x) sW[i] = Wsrc[i];
    for (int i = threadIdx.x; i < D_MID; i += blockDim.x) sb[i] = (which == 0) ? b1[i] : 0.0f;
    __syncthreads();

    int n = blockIdx.x * blockDim.x + threadIdx.x;
    if (n >= N_NODES) return;

    float xr[IN_CH];
    const float4* xp = reinterpret_cast<const float4*>(x + n * IN_CH);
#pragma unroll
    for (int c = 0; c < 8; c++) {
        float4 v = xp[c];
        xr[4 * c + 0] = v.x; xr[4 * c + 1] = v.y; xr[4 * c + 2] = v.z; xr[4 * c + 3] = v.w;
    }

    u64 h[D_MID / 2];
    const ulonglong2* bp = reinterpret_cast<const ulonglong2*>(sb);
#pragma unroll
    for (int j = 0; j < D_MID / 4; j++) {
        ulonglong2 v = bp[j];
        h[2 * j] = v.x; h[2 * j + 1] = v.y;
    }
#pragma unroll
    for (int k = 0; k < IN_CH; k++) {
        u64 aa = pk2(xr[k], xr[k]);
        const ulonglong2* w = reinterpret_cast<const ulonglong2*>(&sW[k * D_MID]);
#pragma unroll
        for (int j = 0; j < D_MID / 4; j++) {
            ulonglong2 ww = w[j];
            FMA2(h[2 * j],     aa, ww.x, h[2 * j]);
            FMA2(h[2 * j + 1], aa, ww.y, h[2 * j + 1]);
        }
    }

    ulonglong2* dst = reinterpret_cast<ulonglong2*>((which == 0 ? g_XR : g_XC) + n * D_MID);
#pragma unroll
    for (int j = 0; j < D_MID / 4; j++) {
        ulonglong2 v; v.x = h[2 * j]; v.y = h[2 * j + 1];
        dst[j] = v;
    }
}

// ---------------------------------------------------------------------------
// K3: per-edge MLP + scatter-max (f32x2 everywhere)
// ---------------------------------------------------------------------------
__device__ __forceinline__ void atomicMaxF(float* addr, float val) {
    if (val >= 0.0f) atomicMax(reinterpret_cast<int*>(addr), __float_as_int(val));
    else             atomicMin(reinterpret_cast<unsigned int*>(addr), __float_as_uint(val));
}

__global__ void __launch_bounds__(128) k_edge(const int* __restrict__ idx32,
                                              const float* __restrict__ edge_attr,
                                              const float* __restrict__ W1,
                                              const float* __restrict__ W2,
                                              const float* __restrict__ b2,
                                              float* __restrict__ out) {
    __shared__ __align__(16) float sWe[EDGE_CH * D_MID];  // W1 rows 64..79
    __shared__ __align__(16) float sW2[D_MID * OUT_CH];
    __shared__ __align__(16) float sb2[OUT_CH];

    const float* We = W1 + 2 * IN_CH * D_MID;
    for (int i = threadIdx.x; i < EDGE_CH * D_MID; i += blockDim.x) sWe[i] = We[i];
    for (int i = threadIdx.x; i < D_MID * OUT_CH; i += blockDim.x) sW2[i] = W2[i];
    for (int i = threadIdx.x; i < OUT_CH; i += blockDim.x) sb2[i] = b2[i];
    __syncthreads();

    int e = blockIdx.x * blockDim.x + threadIdx.x;
    if (e >= N_EDGES) return;

    int rol, col;
    if (g_is64) {
        rol = idx32[2 * e];
        col = idx32[2 * (N_EDGES + e)];
    } else {
        rol = idx32[e];
        col = idx32[N_EDGES + e];
    }

    // ---- layer 1: h = XR[rol] + XC[col] + edge_attr[e] @ We ----
    u64 h[D_MID / 2];
    {
        const ulonglong2* pr = reinterpret_cast<const ulonglong2*>(g_XR + rol * D_MID);
        const ulonglong2* pc = reinterpret_cast<const ulonglong2*>(g_XC + col * D_MID);
#pragma unroll
        for (int j = 0; j < D_MID / 4; j++) {
            ulonglong2 a = pr[j], b = pc[j];
            ADD2(h[2 * j],     a.x, b.x);
            ADD2(h[2 * j + 1], a.y, b.y);
        }
    }
    {
        const float4* pe = reinterpret_cast<const float4*>(edge_attr + e * EDGE_CH);
        float av[EDGE_CH];
#pragma unroll
        for (int c = 0; c < 4; c++) {
            float4 v = pe[c];
            av[4 * c + 0] = v.x; av[4 * c + 1] = v.y; av[4 * c + 2] = v.z; av[4 * c + 3] = v.w;
        }
#pragma unroll
        for (int k = 0; k < EDGE_CH; k++) {
            u64 aa = pk2(av[k], av[k]);
            const ulonglong2* w = reinterpret_cast<const ulonglong2*>(&sWe[k * D_MID]);
#pragma unroll
            for (int j = 0; j < D_MID / 4; j++) {
                ulonglong2 ww = w[j];
                FMA2(h[2 * j],     aa, ww.x, h[2 * j]);
                FMA2(h[2 * j + 1], aa, ww.y, h[2 * j + 1]);
            }
        }
    }

    // ---- LeakyReLU(0.01) -> scalar hs[56] ----
    float hs[D_MID];
#pragma unroll
    for (int j = 0; j < D_MID / 2; j++) {
        float a, b; upk2(a, b, h[j]);
        hs[2 * j]     = fmaxf(a, 0.01f * a);
        hs[2 * j + 1] = fmaxf(b, 0.01f * b);
    }

    // ---- layer 2: o[32] = hs @ W2 + b2 ----
    u64 o[OUT_CH / 2];
    {
        const ulonglong2* bp = reinterpret_cast<const ulonglong2*>(sb2);
#pragma unroll
        for (int j = 0; j < OUT_CH / 4; j++) {
            ulonglong2 v = bp[j];
            o[2 * j] = v.x; o[2 * j + 1] = v.y;
        }
    }
#pragma unroll
    for (int k = 0; k < D_MID; k++) {
        u64 aa = pk2(hs[k], hs[k]);
        const ulonglong2* w = reinterpret_cast<const ulonglong2*>(&sW2[k * OUT_CH]);
#pragma unroll
        for (int j = 0; j < OUT_CH / 4; j++) {
            ulonglong2 ww = w[j];
            FMA2(o[2 * j],     aa, ww.x, o[2 * j]);
            FMA2(o[2 * j + 1], aa, ww.y, o[2 * j + 1]);
        }
    }

    // ---- LeakyReLU + filtered scatter-max ----
    float* orow = out + col * OUT_CH;
    const float4* oro = reinterpret_cast<const float4*>(orow);
#pragma unroll
    for (int q = 0; q < OUT_CH / 4; q++) {
        float v0, v1, v2, v3;
        upk2(v0, v1, o[2 * q]);
        upk2(v2, v3, o[2 * q + 1]);
        v0 = fmaxf(v0, 0.01f * v0);
        v1 = fmaxf(v1, 0.01f * v1);
        v2 = fmaxf(v2, 0.01f * v2);
        v3 = fmaxf(v3, 0.01f * v3);
        float4 cur = oro[q];                 // monotone max: stale read is safe
        if (v0 > cur.x) atomicMaxF(orow + 4 * q + 0, v0);
        if (v1 > cur.y) atomicMaxF(orow + 4 * q + 1, v1);
        if (v2 > cur.z) atomicMaxF(orow + 4 * q + 2, v2);
        if (v3 > cur.w) atomicMaxF(orow + 4 * q + 3, v3);
    }
}

// ---------------------------------------------------------------------------
// K4: finalize — -inf -> 0, elementwise max with x
// ---------------------------------------------------------------------------
__global__ void k_final(const float* __restrict__ x, float* __restrict__ out) {
    int i = blockIdx.x * blockDim.x + threadIdx.x;
    if (i >= N_NODES * OUT_CH) return;
    float a = out[i];
    if (__float_as_uint(a) == 0xFF800000u) a = 0.0f;
    out[i] = fmaxf(a, x[i]);
}

// ---------------------------------------------------------------------------
extern "C" void kernel_launch(void* const* d_in, const int* in_sizes, int n_in,
                              void* d_out, int out_size) {
    const float* x         = (const float*)d_in[0];
    const int*   idx32     = (const int*)d_in[1];
    const float* edge_attr = (const float*)d_in[2];
    const float* W1        = (const float*)d_in[3];
    const float* b1        = (const float*)d_in[4];
    const float* W2        = (const float*)d_in[5];
    const float* b2        = (const float*)d_in[6];
    float* out = (float*)d_out;

    k_detect<<<1, 256>>>((const unsigned int*)d_in[1]);
    k_init<<<(N_NODES * OUT_CH + 255) / 256, 256>>>((unsigned int*)d_out);
    k_node<<<(N_NODES + 127) / 128, 128>>>(x, W1, b1, 0);
    k_node<<<(N_NODES + 127) / 128, 128>>>(x, W1, b1, 1);
    k_edge<<<(N_EDGES + 127) / 128, 128>>>(idx32, edge_attr, W1, W2, b2, out);
    k_final<<<(N_NODES * OUT_CH + 255) / 256, 256>>>(x, out);
}

// round 3
// speedup vs baseline: 1.5200x; 1.0644x over previous
#include <cuda_runtime.h>
#include <cstdint>

#define N_NODES 100000
#define N_EDGES 1000000
#define IN_CH   32
#define EDGE_CH 16
#define OUT_CH  32
#define D_MID   56

typedef unsigned long long u64;

static __device__ int   g_is64;
static __device__ __align__(16) float g_XR[N_NODES * D_MID];  // x @ W1[0:32]  + b1
static __device__ __align__(16) float g_XC[N_NODES * D_MID];  // x @ W1[32:64]

// ---- packed f32x2 helpers ---------------------------------------------------
__device__ __forceinline__ u64 pk2(float a, float b) {
    u64 r; asm("mov.b64 %0, {%1,%2};" : "=l"(r) : "f"(a), "f"(b)); return r;
}
__device__ __forceinline__ void upk2(float& a, float& b, u64 v) {
    asm("mov.b64 {%0,%1}, %2;" : "=f"(a), "=f"(b) : "l"(v));
}
#define FMA2(d, a, b, c) asm("fma.rn.f32x2 %0, %1, %2, %3;" : "=l"(d) : "l"(a), "l"(b), "l"(c))
#define MUL2(d, a, b)    asm("mul.rn.f32x2 %0, %1, %2;"     : "=l"(d) : "l"(a), "l"(b))
#define ADD2(d, a, b)    asm("add.rn.f32x2 %0, %1, %2;"     : "=l"(d) : "l"(a), "l"(b))

// ---------------------------------------------------------------------------
// K0: init output to -inf + (block 0) detect int64 vs int32 edge_index
// ---------------------------------------------------------------------------
__global__ void k_pre(const unsigned int* __restrict__ w, unsigned int* __restrict__ out) {
    if (blockIdx.x == 0) {
        __shared__ int bad;
        if (threadIdx.x == 0) bad = 0;
        __syncthreads();
        for (int i = threadIdx.x; i < 4096; i += blockDim.x)
            if (w[2 * i + 1] != 0u) bad = 1;   // benign race
        __syncthreads();
        if (threadIdx.x == 0) g_is64 = !bad;
    }
    int stride = gridDim.x * blockDim.x;
    for (int i = blockIdx.x * blockDim.x + threadIdx.x; i < N_NODES * OUT_CH; i += stride)
        out[i] = 0xFF800000u;  // -inf
}

// ---------------------------------------------------------------------------
// K1: fused per-node precompute: XR = x@W1[0:32]+b1 and XC = x@W1[32:64]
// ---------------------------------------------------------------------------
__global__ void __launch_bounds__(128) k_node(const float* __restrict__ x,
                                              const float* __restrict__ W1,
                                              const float* __restrict__ b1) {
    __shared__ __align__(16) float sW[2 * IN_CH * D_MID];  // 14336 B
    __shared__ __align__(16) float sb[D_MID];
    for (int i = threadIdx.x; i < 2 * IN_CH * D_MID; i += blockDim.x) sW[i] = W1[i];
    for (int i = threadIdx.x; i < D_MID; i += blockDim.x) sb[i] = b1[i];
    __syncthreads();

    int n = blockIdx.x * blockDim.x + threadIdx.x;
    if (n >= N_NODES) return;

    float xr[IN_CH];
    const float4* xp = reinterpret_cast<const float4*>(x + n * IN_CH);
#pragma unroll
    for (int c = 0; c < 8; c++) {
        float4 v = xp[c];
        xr[4 * c + 0] = v.x; xr[4 * c + 1] = v.y; xr[4 * c + 2] = v.z; xr[4 * c + 3] = v.w;
    }

#pragma unroll
    for (int which = 0; which < 2; which++) {
        u64 h[D_MID / 2];
        if (which == 0) {
            const ulonglong2* bp = reinterpret_cast<const ulonglong2*>(sb);
#pragma unroll
            for (int j = 0; j < D_MID / 4; j++) {
                ulonglong2 v = bp[j];
                h[2 * j] = v.x; h[2 * j + 1] = v.y;
            }
        } else {
#pragma unroll
            for (int j = 0; j < D_MID / 2; j++) h[j] = 0ull;
        }
        const float* Wbase = sW + which * IN_CH * D_MID;
#pragma unroll
        for (int k = 0; k < IN_CH; k++) {
            u64 aa = pk2(xr[k], xr[k]);
            const ulonglong2* w = reinterpret_cast<const ulonglong2*>(Wbase + k * D_MID);
#pragma unroll
            for (int j = 0; j < D_MID / 4; j++) {
                ulonglong2 ww = w[j];
                FMA2(h[2 * j],     aa, ww.x, h[2 * j]);
                FMA2(h[2 * j + 1], aa, ww.y, h[2 * j + 1]);
            }
        }
        ulonglong2* dst = reinterpret_cast<ulonglong2*>((which == 0 ? g_XR : g_XC) + n * D_MID);
#pragma unroll
        for (int j = 0; j < D_MID / 4; j++) {
            ulonglong2 v; v.x = h[2 * j]; v.y = h[2 * j + 1];
            dst[j] = v;
        }
    }
}

// ---------------------------------------------------------------------------
// K2: per-edge MLP + scatter-max
// ---------------------------------------------------------------------------
__device__ __forceinline__ void atomicMaxF(float* addr, float val) {
    if (val >= 0.0f) atomicMax(reinterpret_cast<int*>(addr), __float_as_int(val));
    else             atomicMin(reinterpret_cast<unsigned int*>(addr), __float_as_uint(val));
}

__global__ void __launch_bounds__(128) k_edge(const int* __restrict__ idx32,
                                              const float* __restrict__ edge_attr,
                                              const float* __restrict__ W1,
                                              const float* __restrict__ W2,
                                              const float* __restrict__ b2,
                                              float* __restrict__ out) {
    __shared__ __align__(16) float sWe[EDGE_CH * D_MID];  // W1 rows 64..79
    __shared__ __align__(16) float sW2[D_MID * OUT_CH];
    __shared__ __align__(16) float sb2[OUT_CH];

    const float* We = W1 + 2 * IN_CH * D_MID;
    for (int i = threadIdx.x; i < EDGE_CH * D_MID; i += blockDim.x) sWe[i] = We[i];
    for (int i = threadIdx.x; i < D_MID * OUT_CH; i += blockDim.x) sW2[i] = W2[i];
    for (int i = threadIdx.x; i < OUT_CH; i += blockDim.x) sb2[i] = b2[i];
    __syncthreads();

    int e = blockIdx.x * blockDim.x + threadIdx.x;
    if (e >= N_EDGES) return;

    int rol, col;
    if (g_is64) {
        rol = idx32[2 * e];
        col = idx32[2 * (N_EDGES + e)];
    } else {
        rol = idx32[e];
        col = idx32[N_EDGES + e];
    }
    // Gather addresses known up-front so loads can be hoisted by ptxas.
    const ulonglong2* pr = reinterpret_cast<const ulonglong2*>(g_XR + rol * D_MID);
    const ulonglong2* pc = reinterpret_cast<const ulonglong2*>(g_XC + col * D_MID);

    // ---- layer 1a: h = edge_attr[e] @ We  (shared-memory compute; gathers in flight)
    u64 h[D_MID / 2];
    {
        const float4* pe = reinterpret_cast<const float4*>(edge_attr + e * EDGE_CH);
        float av[EDGE_CH];
#pragma unroll
        for (int c = 0; c < 4; c++) {
            float4 v = pe[c];
            av[4 * c + 0] = v.x; av[4 * c + 1] = v.y; av[4 * c + 2] = v.z; av[4 * c + 3] = v.w;
        }
#pragma unroll
        for (int k = 0; k < EDGE_CH; k++) {
            u64 aa = pk2(av[k], av[k]);
            const ulonglong2* w = reinterpret_cast<const ulonglong2*>(&sWe[k * D_MID]);
#pragma unroll
            for (int j = 0; j < D_MID / 4; j++) {
                ulonglong2 ww = w[j];
                if (k == 0) {
                    MUL2(h[2 * j],     aa, ww.x);
                    MUL2(h[2 * j + 1], aa, ww.y);
                } else {
                    FMA2(h[2 * j],     aa, ww.x, h[2 * j]);
                    FMA2(h[2 * j + 1], aa, ww.y, h[2 * j + 1]);
                }
            }
        }
    }

    // ---- layer 1b: h += XR[rol] + XC[col]
#pragma unroll
    for (int j = 0; j < D_MID / 4; j++) {
        ulonglong2 a = pr[j];
        ulonglong2 b = pc[j];
        ADD2(h[2 * j],     h[2 * j],     a.x);
        ADD2(h[2 * j + 1], h[2 * j + 1], a.y);
        ADD2(h[2 * j],     h[2 * j],     b.x);
        ADD2(h[2 * j + 1], h[2 * j + 1], b.y);
    }

    // ---- layer 2 fused with LeakyReLU, iterating over h pairs (h dies early)
    u64 o[OUT_CH / 2];
    {
        const ulonglong2* bp = reinterpret_cast<const ulonglong2*>(sb2);
#pragma unroll
        for (int j = 0; j < OUT_CH / 4; j++) {
            ulonglong2 v = bp[j];
            o[2 * j] = v.x; o[2 * j + 1] = v.y;
        }
    }
#pragma unroll
    for (int p = 0; p < D_MID / 2; p++) {
        float a, b; upk2(a, b, h[p]);
        a = fmaxf(a, 0.01f * a);
        b = fmaxf(b, 0.01f * b);
        u64 aa = pk2(a, a);
        u64 bb = pk2(b, b);
        const ulonglong2* wa = reinterpret_cast<const ulonglong2*>(&sW2[(2 * p) * OUT_CH]);
        const ulonglong2* wb = reinterpret_cast<const ulonglong2*>(&sW2[(2 * p + 1) * OUT_CH]);
#pragma unroll
        for (int j = 0; j < OUT_CH / 4; j++) {
            ulonglong2 w0 = wa[j];
            FMA2(o[2 * j],     aa, w0.x, o[2 * j]);
            FMA2(o[2 * j + 1], aa, w0.y, o[2 * j + 1]);
            ulonglong2 w1 = wb[j];
            FMA2(o[2 * j],     bb, w1.x, o[2 * j]);
            FMA2(o[2 * j + 1], bb, w1.y, o[2 * j + 1]);
        }
    }

    // ---- LeakyReLU + filtered scatter-max ----
    float* orow = out + col * OUT_CH;
    const float4* oro = reinterpret_cast<const float4*>(orow);
#pragma unroll
    for (int q = 0; q < OUT_CH / 4; q++) {
        float v0, v1, v2, v3;
        upk2(v0, v1, o[2 * q]);
        upk2(v2, v3, o[2 * q + 1]);
        v0 = fmaxf(v0, 0.01f * v0);
        v1 = fmaxf(v1, 0.01f * v1);
        v2 = fmaxf(v2, 0.01f * v2);
        v3 = fmaxf(v3, 0.01f * v3);
        float4 cur = oro[q];                 // monotone max: stale read is safe
        if (v0 > cur.x) atomicMaxF(orow + 4 * q + 0, v0);
        if (v1 > cur.y) atomicMaxF(orow + 4 * q + 1, v1);
        if (v2 > cur.z) atomicMaxF(orow + 4 * q + 2, v2);
        if (v3 > cur.w) atomicMaxF(orow + 4 * q + 3, v3);
    }
}

// ---------------------------------------------------------------------------
// K3: finalize — -inf -> 0, elementwise max with x
// ---------------------------------------------------------------------------
__global__ void k_final(const float* __restrict__ x, float* __restrict__ out) {
    int i = blockIdx.x * blockDim.x + threadIdx.x;
    if (i >= N_NODES * OUT_CH) return;
    float a = out[i];
    if (__float_as_uint(a) == 0xFF800000u) a = 0.0f;
    out[i] = fmaxf(a, x[i]);
}

// ---------------------------------------------------------------------------
extern "C" void kernel_launch(void* const* d_in, const int* in_sizes, int n_in,
                              void* d_out, int out_size) {
    const float* x         = (const float*)d_in[0];
    const int*   idx32     = (const int*)d_in[1];
    const float* edge_attr = (const float*)d_in[2];
    const float* W1        = (const float*)d_in[3];
    const float* b1        = (const float*)d_in[4];
    const float* W2        = (const float*)d_in[5];
    const float* b2        = (const float*)d_in[6];
    float* out = (float*)d_out;

    k_pre<<<592, 256>>>((const unsigned int*)d_in[1], (unsigned int*)d_out);
    k_node<<<(N_NODES + 127) / 128, 128>>>(x, W1, b1);
    k_edge<<<(N_EDGES + 127) / 128, 128>>>(idx32, edge_attr, W1, W2, b2, out);
    k_final<<<(N_NODES * OUT_CH + 255) / 256, 256>>>(x, out);
}